// round 13
// baseline (speedup 1.0000x reference)
#include <cuda_runtime.h>
#include <cuda_fp16.h>
#include <cuda_pipeline.h>
#include <mma.h>
#include <stdint.h>

using namespace nvcuda;

#define N_NODES 10000
#define D 256
#define ROW_WORDS 320   // ceil(10000/32)=313, padded to 320 (1280 B/row)

// ---------------- scratch (device globals; no allocation allowed) ----------
__device__ __align__(16) unsigned int g_bitmap[N_NODES * ROW_WORDS];  // 12.8 MB
__device__ float g_dinv[N_NODES];
__device__ __align__(16) __half g_zs_h[N_NODES * D];     // fp16 dinv[j]*(x@W)[j,:]
__device__ int g_mode;   // 0 = int32 edge layout, 1 = raw int64 layout

// ---------------------------------------------------------------------------
// Zero bitmap (all blocks) + edge-layout detection (block 0)
__global__ void zero_detect_kernel(const int* __restrict__ ei, int n_words) {
    int idx = blockIdx.x * blockDim.x + threadIdx.x;
    const int total = N_NODES * ROW_WORDS / 4;
    uint4 z = make_uint4(0u, 0u, 0u, 0u);
    for (int i = idx; i < total; i += gridDim.x * blockDim.x)
        ((uint4*)g_bitmap)[i] = z;

    if (blockIdx.x == 0) {
        __shared__ unsigned int s_or[8];
        int t = threadIdx.x;           // 256 threads, check 512 odd words
        unsigned int v = 0;
        int i0 = 4 * t + 1, i1 = 4 * t + 3;
        if (i0 < n_words) v |= (unsigned int)ei[i0];
        if (i1 < n_words) v |= (unsigned int)ei[i1];
        #pragma unroll
        for (int o = 16; o > 0; o >>= 1) v |= __shfl_down_sync(0xffffffffu, v, o);
        if ((t & 31) == 0) s_or[t >> 5] = v;
        __syncthreads();
        if (t == 0) {
            unsigned int r = 0;
            #pragma unroll
            for (int w2 = 0; w2 < 8; w2++) r |= s_or[w2];
            g_mode = (r == 0u) ? 1 : 0;   // all-zero odd words => int64
        }
    }
}

// 2 edges per thread, vector loads; idempotent atomicOr = exact dedup
__global__ void set_edges_kernel(const int* __restrict__ ei, int E) {
    int t = blockIdx.x * blockDim.x + threadIdx.x;
    int base = t * 2;
    if (base >= E) return;
    int s[2], d[2];
    bool vec = ((E & 1) == 0) && (base + 1 < E);
    if (g_mode) {
        if (vec) {
            int4 a = ((const int4*)ei)[t];
            int4 b = ((const int4*)(ei + 2 * E))[t];
            s[0] = a.x; s[1] = a.z;
            d[0] = b.x; d[1] = b.z;
        } else {
            #pragma unroll
            for (int q = 0; q < 2; q++) {
                int e = base + q;
                s[q] = (e < E) ? ei[2 * e] : -1;
                d[q] = (e < E) ? ei[2 * E + 2 * e] : -1;
            }
        }
    } else {
        if (vec) {
            int2 a = ((const int2*)ei)[t];
            int2 b = ((const int2*)(ei + E))[t];
            s[0] = a.x; s[1] = a.y;
            d[0] = b.x; d[1] = b.y;
        } else {
            #pragma unroll
            for (int q = 0; q < 2; q++) {
                int e = base + q;
                s[q] = (e < E) ? ei[e] : -1;
                d[q] = (e < E) ? ei[E + e] : -1;
            }
        }
    }
    #pragma unroll
    for (int q = 0; q < 2; q++) {
        if ((unsigned)s[q] < N_NODES && (unsigned)d[q] < N_NODES) {
            atomicOr(&g_bitmap[s[q] * ROW_WORDS + (d[q] >> 5)], 1u << (d[q] & 31));
            atomicOr(&g_bitmap[d[q] * ROW_WORDS + (s[q] >> 5)], 1u << (s[q] & 31));
        }
    }
}

// One warp per row: deg = popcount(row) + 1; REDUX reduction
__global__ void dinv_kernel() {
    int warp = (blockIdx.x * blockDim.x + threadIdx.x) >> 5;
    int lane = threadIdx.x & 31;
    if (warp >= N_NODES) return;
    const uint4* row = (const uint4*)&g_bitmap[warp * ROW_WORDS];  // 80 uint4
    int cnt = 0;
    #pragma unroll
    for (int t = 0; t < 3; t++) {
        int idx = lane + t * 32;
        if (idx < 80) {
            uint4 v = row[idx];
            cnt += __popc(v.x) + __popc(v.y) + __popc(v.z) + __popc(v.w);
        }
    }
    cnt = __reduce_add_sync(0xffffffffu, cnt);
    if (lane == 0) g_dinv[warp] = rsqrtf((float)(cnt + 1));
}

// ---------------------------------------------------------------------------
// TF32 wmma GEMM, cp.async double-buffered:
//   zs[m,n] = fp16( dinv[m] * sum_k x[m,k] * W[k,n] )
// CTA tile 128(M) x 128(N), BK=32, 8 warps (2 M x 4 N), warp tile 64x32.
#define BKC 32
#define LDA 36    // 128 x 36 f32 (144 B/row, 16B-mult)
#define LDB 132   // 32 x 132 f32 (528 B/row, 16B-mult)
#define LDC 132
#define A_BYTES (128 * LDA * 4)          // 18432
#define B_OFF   A_BYTES
#define BUF_BYTES (A_BYTES + 32 * LDB * 4)   // 35328
#define SMEM_GEMM (2 * BUF_BYTES)            // 70656 >= 128*132*4 epilogue

__global__ __launch_bounds__(256) void gemm_tf32_kernel(
    const float* __restrict__ x, const float* __restrict__ w)
{
    extern __shared__ char smem[];
    float* sC = (float*)smem;

    int tid = threadIdx.x;
    int wid = tid >> 5;
    int warp_m = wid & 1;        // 0..1  (64 rows)
    int warp_n = wid >> 1;       // 0..3  (32 cols)
    int bm = blockIdx.x * 128;
    int bn = blockIdx.y * 128;

    wmma::fragment<wmma::accumulator, 16, 16, 8, float> acc[4][2];
    #pragma unroll
    for (int mi = 0; mi < 4; mi++)
        #pragma unroll
        for (int ni = 0; ni < 2; ni++)
            wmma::fill_fragment(acc[mi][ni], 0.0f);

    // cp.async issue for one k-chunk into buffer `buf`
    auto issue = [&](int buf, int k0) {
        char* base = smem + buf * BUF_BYTES;
        float* sA = (float*)base;
        float* sB = (float*)(base + B_OFF);
        // A: 128 rows x 32 f32 = 1024 x 16B; 8 slots per row -> row=lin>>3, q=lin&7
        #pragma unroll
        for (int t = 0; t < 4; t++) {
            int lin = tid + t * 256;
            int row = lin >> 3, q = lin & 7;
            int m = bm + row;
            const float* src = (m < N_NODES) ? &x[(size_t)m * D + k0 + q * 4] : x;
            size_t zf = (m < N_NODES) ? 0 : 16;
            __pipeline_memcpy_async(&sA[row * LDA + q * 4], src, 16, zf);
        }
        // B: 32 rows x 128 f32 = 1024 x 16B; 32 slots per row -> kr=lin>>5, nq=lin&31
        #pragma unroll
        for (int t = 0; t < 4; t++) {
            int lin = tid + t * 256;
            int kr = lin >> 5, nq = lin & 31;
            __pipeline_memcpy_async(&sB[kr * LDB + nq * 4],
                                    &w[(size_t)(k0 + kr) * D + bn + nq * 4], 16);
        }
    };

    issue(0, 0);
    __pipeline_commit();

    for (int kc = 0; kc < 8; kc++) {
        if (kc < 7) {
            issue((kc + 1) & 1, (kc + 1) * BKC);
            __pipeline_commit();
            __pipeline_wait_prior(1);
        } else {
            __pipeline_wait_prior(0);
        }
        __syncthreads();

        char* base = smem + (kc & 1) * BUF_BYTES;
        float* sA = (float*)base;
        float* sB = (float*)(base + B_OFF);
        #pragma unroll
        for (int ks = 0; ks < 4; ks++) {
            int kk = ks * 8;
            wmma::fragment<wmma::matrix_b, 16, 16, 8, wmma::precision::tf32,
                           wmma::row_major> bfr[2];
            #pragma unroll
            for (int ni = 0; ni < 2; ni++) {
                wmma::load_matrix_sync(bfr[ni], &sB[kk * LDB + warp_n * 32 + ni * 16], LDB);
                #pragma unroll
                for (int e = 0; e < bfr[ni].num_elements; e++)
                    bfr[ni].x[e] = wmma::__float_to_tf32(bfr[ni].x[e]);
            }
            #pragma unroll
            for (int mi = 0; mi < 4; mi++) {
                wmma::fragment<wmma::matrix_a, 16, 16, 8, wmma::precision::tf32,
                               wmma::row_major> afr;
                wmma::load_matrix_sync(afr, &sA[(warp_m * 64 + mi * 16) * LDA + kk], LDA);
                #pragma unroll
                for (int e = 0; e < afr.num_elements; e++)
                    afr.x[e] = wmma::__float_to_tf32(afr.x[e]);
                #pragma unroll
                for (int ni = 0; ni < 2; ni++)
                    wmma::mma_sync(acc[mi][ni], afr, bfr[ni], acc[mi][ni]);
            }
        }
        __syncthreads();   // all warps done with this buffer before it's refilled
    }

    // Epilogue: frags -> smem -> scale by dinv -> g_zs_h (fp16)
    #pragma unroll
    for (int mi = 0; mi < 4; mi++)
        #pragma unroll
        for (int ni = 0; ni < 2; ni++)
            wmma::store_matrix_sync(
                &sC[(warp_m * 64 + mi * 16) * LDC + warp_n * 32 + ni * 16],
                acc[mi][ni], LDC, wmma::mem_row_major);
    __syncthreads();

    #pragma unroll
    for (int t = 0; t < 16; t++) {
        int lin = tid + t * 256;
        int row = lin >> 5, c4 = lin & 31;
        int m = bm + row;
        if (m < N_NODES) {
            float dv = g_dinv[m];
            float4 v = *(float4*)&sC[row * LDC + c4 * 4];
            __half2 h01 = __floats2half2_rn(v.x * dv, v.y * dv);
            __half2 h23 = __floats2half2_rn(v.z * dv, v.w * dv);
            uint2 o;
            o.x = *(unsigned int*)&h01;
            o.y = *(unsigned int*)&h23;
            *(uint2*)&g_zs_h[(size_t)m * D + bn + c4 * 4] = o;
        }
    }
}

// ---------------------------------------------------------------------------
// SpMM over the bitmap: out[i,:] = dinv[i] * (sum_{bit(i,j)} zs[j,:] + zs[i,:])
#define SCHUNK 128
#define SCAP (SCHUNK * 32)

__global__ __launch_bounds__(128) void spmm_kernel(float* __restrict__ out) {
    __shared__ int s_idx[SCAP];
    __shared__ int s_cnt;
    int i = blockIdx.x;
    int t = threadIdx.x;                         // dim pair t -> dims 2t, 2t+1
    const unsigned int* row = &g_bitmap[i * ROW_WORDS];
    const __half2* zs2 = (const __half2*)g_zs_h;

    float2 a0 = {0.f, 0.f}, a1 = {0.f, 0.f}, a2 = {0.f, 0.f}, a3 = {0.f, 0.f};

    for (int cw = 0; cw < ROW_WORDS; cw += SCHUNK) {
        if (t == 0) s_cnt = 0;
        __syncthreads();
        int w = cw + t;
        unsigned int bits = (w < ROW_WORDS) ? row[w] : 0u;
        while (bits) {
            int b = __ffs(bits) - 1;
            bits &= bits - 1;
            s_idx[atomicAdd(&s_cnt, 1)] = (w << 5) + b;
        }
        __syncthreads();
        int nb = s_cnt;
        int k = 0;
        for (; k + 4 <= nb; k += 4) {
            int j0 = s_idx[k + 0];
            int j1 = s_idx[k + 1];
            int j2 = s_idx[k + 2];
            int j3 = s_idx[k + 3];
            float2 v0 = __half22float2(zs2[(size_t)j0 * 128 + t]);
            float2 v1 = __half22float2(zs2[(size_t)j1 * 128 + t]);
            float2 v2 = __half22float2(zs2[(size_t)j2 * 128 + t]);
            float2 v3 = __half22float2(zs2[(size_t)j3 * 128 + t]);
            a0.x += v0.x; a0.y += v0.y;
            a1.x += v1.x; a1.y += v1.y;
            a2.x += v2.x; a2.y += v2.y;
            a3.x += v3.x; a3.y += v3.y;
        }
        for (; k < nb; k++) {
            float2 v = __half22float2(zs2[(size_t)s_idx[k] * 128 + t]);
            a0.x += v.x; a0.y += v.y;
        }
        __syncthreads();
    }

    float2 self = __half22float2(zs2[(size_t)i * 128 + t]);
    float dv = g_dinv[i];
    float2 r;
    r.x = dv * ((a0.x + a1.x) + (a2.x + a3.x) + self.x);
    r.y = dv * ((a0.y + a1.y) + (a2.y + a3.y) + self.y);
    ((float2*)out)[(size_t)i * 128 + t] = r;
}

// ---------------------------------------------------------------------------
extern "C" void kernel_launch(void* const* d_in, const int* in_sizes, int n_in,
                              void* d_out, int out_size) {
    const float* x = (const float*)d_in[0];
    const int* ei = (const int*)d_in[1];
    const float* w = (const float*)d_in[2];
    float* out = (float*)d_out;
    int E = in_sizes[1] / 2;

    cudaFuncSetAttribute(gemm_tf32_kernel,
                         cudaFuncAttributeMaxDynamicSharedMemorySize, SMEM_GEMM);

    zero_detect_kernel<<<1024, 256>>>(ei, 2 * E);
    set_edges_kernel<<<(E / 2 + 255) / 256, 256>>>(ei, E);
    dinv_kernel<<<(N_NODES * 32 + 255) / 256, 256>>>();

    dim3 ggrid((N_NODES + 127) / 128, D / 128);
    gemm_tf32_kernel<<<ggrid, 256, SMEM_GEMM>>>(x, w);

    spmm_kernel<<<N_NODES, 128>>>(out);
}

// round 14
// speedup vs baseline: 1.8051x; 1.8051x over previous
#include <cuda_runtime.h>
#include <cuda_bf16.h>
#include <cuda_fp16.h>
#include <cuda_pipeline.h>
#include <mma.h>
#include <stdint.h>

using namespace nvcuda;

#define N_NODES 10000
#define D 256
#define ROW_WORDS 320   // ceil(10000/32)=313, padded to 320 (1280 B/row)

// ---------------- scratch (device globals; no allocation allowed) ----------
__device__ __align__(16) unsigned int g_bitmap[N_NODES * ROW_WORDS];  // 12.8 MB
__device__ float g_dinv[N_NODES];
__device__ __align__(16) __half g_zs_h[N_NODES * D];       // fp16 dinv[j]*(x@W)[j,:]
__device__ __align__(16) __nv_bfloat16 g_xh[N_NODES * D];  // x hi [m][k]
__device__ __align__(16) __nv_bfloat16 g_xl[N_NODES * D];  // x lo [m][k]
__device__ __align__(16) __nv_bfloat16 g_wh[D * D];        // W hi [k][n]
__device__ __align__(16) __nv_bfloat16 g_wl[D * D];        // W lo [k][n]
__device__ int g_mode;   // 0 = int32 edge layout, 1 = raw int64 layout

// ---------------------------------------------------------------------------
__device__ __forceinline__ unsigned long long split4(float4 v, unsigned long long& lo) {
    unsigned short h0 = __bfloat16_as_ushort(__float2bfloat16(v.x));
    unsigned short h1 = __bfloat16_as_ushort(__float2bfloat16(v.y));
    unsigned short h2 = __bfloat16_as_ushort(__float2bfloat16(v.z));
    unsigned short h3 = __bfloat16_as_ushort(__float2bfloat16(v.w));
    float f0 = __uint_as_float((unsigned)h0 << 16);
    float f1 = __uint_as_float((unsigned)h1 << 16);
    float f2 = __uint_as_float((unsigned)h2 << 16);
    float f3 = __uint_as_float((unsigned)h3 << 16);
    unsigned short l0 = __bfloat16_as_ushort(__float2bfloat16(v.x - f0));
    unsigned short l1 = __bfloat16_as_ushort(__float2bfloat16(v.y - f1));
    unsigned short l2 = __bfloat16_as_ushort(__float2bfloat16(v.z - f2));
    unsigned short l3 = __bfloat16_as_ushort(__float2bfloat16(v.w - f3));
    lo = (unsigned long long)l0 | ((unsigned long long)l1 << 16)
       | ((unsigned long long)l2 << 32) | ((unsigned long long)l3 << 48);
    return (unsigned long long)h0 | ((unsigned long long)h1 << 16)
         | ((unsigned long long)h2 << 32) | ((unsigned long long)h3 << 48);
}

// Split x (all threads) and W (first threads) into bf16 hi/lo
__global__ void prep_kernel(const float* __restrict__ x, const float* __restrict__ w) {
    int idx = blockIdx.x * blockDim.x + threadIdx.x;
    const int NX4 = N_NODES * D / 4;   // 640000
    if (idx < NX4) {
        unsigned long long lo;
        unsigned long long hi = split4(((const float4*)x)[idx], lo);
        *(unsigned long long*)&g_xh[idx * 4] = hi;
        *(unsigned long long*)&g_xl[idx * 4] = lo;
    }
    if (idx < D * D / 4) {             // 16384
        unsigned long long lo;
        unsigned long long hi = split4(((const float4*)w)[idx], lo);
        *(unsigned long long*)&g_wh[idx * 4] = hi;
        *(unsigned long long*)&g_wl[idx * 4] = lo;
    }
}

// Zero bitmap (all blocks) + edge-layout detection (block 0)
__global__ void zero_detect_kernel(const int* __restrict__ ei, int n_words) {
    int idx = blockIdx.x * blockDim.x + threadIdx.x;
    const int total = N_NODES * ROW_WORDS / 4;
    uint4 z = make_uint4(0u, 0u, 0u, 0u);
    for (int i = idx; i < total; i += gridDim.x * blockDim.x)
        ((uint4*)g_bitmap)[i] = z;

    if (blockIdx.x == 0) {
        __shared__ unsigned int s_or[8];
        int t = threadIdx.x;           // 256 threads, check 512 odd words
        unsigned int v = 0;
        int i0 = 4 * t + 1, i1 = 4 * t + 3;
        if (i0 < n_words) v |= (unsigned int)ei[i0];
        if (i1 < n_words) v |= (unsigned int)ei[i1];
        #pragma unroll
        for (int o = 16; o > 0; o >>= 1) v |= __shfl_down_sync(0xffffffffu, v, o);
        if ((t & 31) == 0) s_or[t >> 5] = v;
        __syncthreads();
        if (t == 0) {
            unsigned int r = 0;
            #pragma unroll
            for (int w2 = 0; w2 < 8; w2++) r |= s_or[w2];
            g_mode = (r == 0u) ? 1 : 0;   // all-zero odd words => int64
        }
    }
}

// 2 edges per thread, vector loads; idempotent atomicOr = exact dedup
__global__ void set_edges_kernel(const int* __restrict__ ei, int E) {
    int t = blockIdx.x * blockDim.x + threadIdx.x;
    int base = t * 2;
    if (base >= E) return;
    int s[2], d[2];
    bool vec = ((E & 1) == 0) && (base + 1 < E);
    if (g_mode) {
        if (vec) {
            int4 a = ((const int4*)ei)[t];
            int4 b = ((const int4*)(ei + 2 * E))[t];
            s[0] = a.x; s[1] = a.z;
            d[0] = b.x; d[1] = b.z;
        } else {
            #pragma unroll
            for (int q = 0; q < 2; q++) {
                int e = base + q;
                s[q] = (e < E) ? ei[2 * e] : -1;
                d[q] = (e < E) ? ei[2 * E + 2 * e] : -1;
            }
        }
    } else {
        if (vec) {
            int2 a = ((const int2*)ei)[t];
            int2 b = ((const int2*)(ei + E))[t];
            s[0] = a.x; s[1] = a.y;
            d[0] = b.x; d[1] = b.y;
        } else {
            #pragma unroll
            for (int q = 0; q < 2; q++) {
                int e = base + q;
                s[q] = (e < E) ? ei[e] : -1;
                d[q] = (e < E) ? ei[E + e] : -1;
            }
        }
    }
    #pragma unroll
    for (int q = 0; q < 2; q++) {
        if ((unsigned)s[q] < N_NODES && (unsigned)d[q] < N_NODES) {
            atomicOr(&g_bitmap[s[q] * ROW_WORDS + (d[q] >> 5)], 1u << (d[q] & 31));
            atomicOr(&g_bitmap[d[q] * ROW_WORDS + (s[q] >> 5)], 1u << (s[q] & 31));
        }
    }
}

// One warp per row: deg = popcount(row) + 1; REDUX reduction
__global__ void dinv_kernel() {
    int warp = (blockIdx.x * blockDim.x + threadIdx.x) >> 5;
    int lane = threadIdx.x & 31;
    if (warp >= N_NODES) return;
    const uint4* row = (const uint4*)&g_bitmap[warp * ROW_WORDS];  // 80 uint4
    int cnt = 0;
    #pragma unroll
    for (int t = 0; t < 3; t++) {
        int idx = lane + t * 32;
        if (idx < 80) {
            uint4 v = row[idx];
            cnt += __popc(v.x) + __popc(v.y) + __popc(v.z) + __popc(v.w);
        }
    }
    cnt = __reduce_add_sync(0xffffffffu, cnt);
    if (lane == 0) g_dinv[warp] = rsqrtf((float)(cnt + 1));
}

// ---------------------------------------------------------------------------
// bf16 3-term wmma GEMM, cp.async double-buffered, high occupancy:
//   zs[m,n] = fp16( dinv[m] * sum_k x[m,k] * W[k,n] )
// CTA tile 64(M) x 64(N), BK=32, 128 threads / 4 warps (2 M x 2 N),
// warp tile 32x32. Operands pre-split bf16 hi/lo.
#define BKC 32
#define LDA 40    // 64 x 40 bf16 (80 B/row)
#define LDB 72    // 32 x 72 bf16 (144 B/row)
#define LDC 68    // 64 x 68 f32
#define A_ONE (64 * LDA * 2)                 // 5120 B (one of hi/lo)
#define B_ONE (32 * LDB * 2)                 // 4608 B
#define AH_OFF 0
#define AL_OFF A_ONE
#define BH_OFF (2 * A_ONE)
#define BL_OFF (2 * A_ONE + B_ONE)
#define BUF_BYTES (2 * A_ONE + 2 * B_ONE)    // 19456
#define SMEM_GEMM (2 * BUF_BYTES)            // 38912 >= 64*68*4=17408 epilogue

__global__ __launch_bounds__(128, 4) void gemm_bf16_kernel() {
    extern __shared__ char smem[];
    float* sC = (float*)smem;

    int tid = threadIdx.x;
    int wid = tid >> 5;
    int warp_m = wid & 1;        // 0..1 (32 rows)
    int warp_n = wid >> 1;       // 0..1 (32 cols)
    int bm = blockIdx.x * 64;
    int bn = blockIdx.y * 64;

    wmma::fragment<wmma::accumulator, 16, 16, 16, float> acc[2][2];
    #pragma unroll
    for (int mi = 0; mi < 2; mi++)
        #pragma unroll
        for (int ni = 0; ni < 2; ni++)
            wmma::fill_fragment(acc[mi][ni], 0.0f);

    // cp.async one k-chunk into buffer `buf`
    auto issue = [&](int buf, int k0) {
        char* base = smem + buf * BUF_BYTES;
        __nv_bfloat16* sAh = (__nv_bfloat16*)(base + AH_OFF);
        __nv_bfloat16* sAl = (__nv_bfloat16*)(base + AL_OFF);
        __nv_bfloat16* sBh = (__nv_bfloat16*)(base + BH_OFF);
        __nv_bfloat16* sBl = (__nv_bfloat16*)(base + BL_OFF);
        // A: 64 rows x 32 bf16 = 256 x 16B per matrix; row=lin>>2, q=lin&3
        #pragma unroll
        for (int t = 0; t < 2; t++) {
            int lin = tid + t * 128;
            int row = lin >> 2, q = lin & 3;
            int m = bm + row;
            size_t gi = (size_t)((m < N_NODES) ? m : 0) * D + k0 + q * 8;
            size_t zf = (m < N_NODES) ? 0 : 16;
            __pipeline_memcpy_async(&sAh[row * LDA + q * 8], &g_xh[gi], 16, zf);
            __pipeline_memcpy_async(&sAl[row * LDA + q * 8], &g_xl[gi], 16, zf);
        }
        // B: 32 rows x 64 bf16 = 256 x 16B per matrix; kr=lin>>3, nq=lin&7
        #pragma unroll
        for (int t = 0; t < 2; t++) {
            int lin = tid + t * 128;
            int kr = lin >> 3, nq = lin & 7;
            size_t gi = (size_t)(k0 + kr) * D + bn + nq * 8;
            __pipeline_memcpy_async(&sBh[kr * LDB + nq * 8], &g_wh[gi], 16);
            __pipeline_memcpy_async(&sBl[kr * LDB + nq * 8], &g_wl[gi], 16);
        }
    };

    issue(0, 0);
    __pipeline_commit();

    for (int kc = 0; kc < 8; kc++) {
        if (kc < 7) {
            issue((kc + 1) & 1, (kc + 1) * BKC);
            __pipeline_commit();
            __pipeline_wait_prior(1);
        } else {
            __pipeline_wait_prior(0);
        }
        __syncthreads();

        char* base = smem + (kc & 1) * BUF_BYTES;
        __nv_bfloat16* sAh = (__nv_bfloat16*)(base + AH_OFF);
        __nv_bfloat16* sAl = (__nv_bfloat16*)(base + AL_OFF);
        __nv_bfloat16* sBh = (__nv_bfloat16*)(base + BH_OFF);
        __nv_bfloat16* sBl = (__nv_bfloat16*)(base + BL_OFF);

        #pragma unroll
        for (int kk = 0; kk < 32; kk += 16) {
            wmma::fragment<wmma::matrix_b, 16, 16, 16, __nv_bfloat16, wmma::row_major> bh[2], bl[2];
            #pragma unroll
            for (int ni = 0; ni < 2; ni++) {
                wmma::load_matrix_sync(bh[ni], &sBh[kk * LDB + warp_n * 32 + ni * 16], LDB);
                wmma::load_matrix_sync(bl[ni], &sBl[kk * LDB + warp_n * 32 + ni * 16], LDB);
            }
            #pragma unroll
            for (int mi = 0; mi < 2; mi++) {
                wmma::fragment<wmma::matrix_a, 16, 16, 16, __nv_bfloat16, wmma::row_major> ah, al;
                wmma::load_matrix_sync(ah, &sAh[(warp_m * 32 + mi * 16) * LDA + kk], LDA);
                wmma::load_matrix_sync(al, &sAl[(warp_m * 32 + mi * 16) * LDA + kk], LDA);
                #pragma unroll
                for (int ni = 0; ni < 2; ni++) {
                    wmma::mma_sync(acc[mi][ni], ah, bh[ni], acc[mi][ni]);
                    wmma::mma_sync(acc[mi][ni], ah, bl[ni], acc[mi][ni]);
                    wmma::mma_sync(acc[mi][ni], al, bh[ni], acc[mi][ni]);
                }
            }
        }
        __syncthreads();   // buffer consumed before refill next iteration
    }

    // Epilogue: frags -> smem -> scale by dinv -> g_zs_h (fp16)
    #pragma unroll
    for (int mi = 0; mi < 2; mi++)
        #pragma unroll
        for (int ni = 0; ni < 2; ni++)
            wmma::store_matrix_sync(
                &sC[(warp_m * 32 + mi * 16) * LDC + warp_n * 32 + ni * 16],
                acc[mi][ni], LDC, wmma::mem_row_major);
    __syncthreads();

    // 64 rows x 64 cols: 1024 groups of 4 -> 8 per thread
    #pragma unroll
    for (int t = 0; t < 8; t++) {
        int lin = tid + t * 128;
        int row = lin >> 4, c4 = lin & 15;
        int m = bm + row;
        if (m < N_NODES) {
            float dv = g_dinv[m];
            float4 v = *(float4*)&sC[row * LDC + c4 * 4];
            __half2 h01 = __floats2half2_rn(v.x * dv, v.y * dv);
            __half2 h23 = __floats2half2_rn(v.z * dv, v.w * dv);
            uint2 o;
            o.x = *(unsigned int*)&h01;
            o.y = *(unsigned int*)&h23;
            *(uint2*)&g_zs_h[(size_t)m * D + bn + c4 * 4] = o;
        }
    }
}

// ---------------------------------------------------------------------------
// SpMM over the bitmap: out[i,:] = dinv[i] * (sum_{bit(i,j)} zs[j,:] + zs[i,:])
#define SCHUNK 128
#define SCAP (SCHUNK * 32)

__global__ __launch_bounds__(128) void spmm_kernel(float* __restrict__ out) {
    __shared__ int s_idx[SCAP];
    __shared__ int s_cnt;
    int i = blockIdx.x;
    int t = threadIdx.x;                         // dim pair t -> dims 2t, 2t+1
    const unsigned int* row = &g_bitmap[i * ROW_WORDS];
    const __half2* zs2 = (const __half2*)g_zs_h;

    float2 a0 = {0.f, 0.f}, a1 = {0.f, 0.f}, a2 = {0.f, 0.f}, a3 = {0.f, 0.f};

    for (int cw = 0; cw < ROW_WORDS; cw += SCHUNK) {
        if (t == 0) s_cnt = 0;
        __syncthreads();
        int w = cw + t;
        unsigned int bits = (w < ROW_WORDS) ? row[w] : 0u;
        while (bits) {
            int b = __ffs(bits) - 1;
            bits &= bits - 1;
            s_idx[atomicAdd(&s_cnt, 1)] = (w << 5) + b;
        }
        __syncthreads();
        int nb = s_cnt;
        int k = 0;
        for (; k + 4 <= nb; k += 4) {
            int j0 = s_idx[k + 0];
            int j1 = s_idx[k + 1];
            int j2 = s_idx[k + 2];
            int j3 = s_idx[k + 3];
            float2 v0 = __half22float2(zs2[(size_t)j0 * 128 + t]);
            float2 v1 = __half22float2(zs2[(size_t)j1 * 128 + t]);
            float2 v2 = __half22float2(zs2[(size_t)j2 * 128 + t]);
            float2 v3 = __half22float2(zs2[(size_t)j3 * 128 + t]);
            a0.x += v0.x; a0.y += v0.y;
            a1.x += v1.x; a1.y += v1.y;
            a2.x += v2.x; a2.y += v2.y;
            a3.x += v3.x; a3.y += v3.y;
        }
        for (; k < nb; k++) {
            float2 v = __half22float2(zs2[(size_t)s_idx[k] * 128 + t]);
            a0.x += v.x; a0.y += v.y;
        }
        __syncthreads();
    }

    float2 self = __half22float2(zs2[(size_t)i * 128 + t]);
    float dv = g_dinv[i];
    float2 r;
    r.x = dv * ((a0.x + a1.x) + (a2.x + a3.x) + self.x);
    r.y = dv * ((a0.y + a1.y) + (a2.y + a3.y) + self.y);
    ((float2*)out)[(size_t)i * 128 + t] = r;
}

// ---------------------------------------------------------------------------
extern "C" void kernel_launch(void* const* d_in, const int* in_sizes, int n_in,
                              void* d_out, int out_size) {
    const float* x = (const float*)d_in[0];
    const int* ei = (const int*)d_in[1];
    const float* w = (const float*)d_in[2];
    float* out = (float*)d_out;
    int E = in_sizes[1] / 2;

    cudaFuncSetAttribute(gemm_bf16_kernel,
                         cudaFuncAttributeMaxDynamicSharedMemorySize, SMEM_GEMM);

    prep_kernel<<<(N_NODES * D / 4 + 255) / 256, 256>>>(x, w);
    zero_detect_kernel<<<1024, 256>>>(ei, 2 * E);
    set_edges_kernel<<<(E / 2 + 255) / 256, 256>>>(ei, E);
    dinv_kernel<<<(N_NODES * 32 + 255) / 256, 256>>>();

    dim3 ggrid((N_NODES + 63) / 64, D / 64);
    gemm_bf16_kernel<<<ggrid, 128, SMEM_GEMM>>>();

    spmm_kernel<<<N_NODES, 128>>>(out);
}

// round 15
// speedup vs baseline: 2.0913x; 1.1585x over previous
#include <cuda_runtime.h>
#include <cuda_fp16.h>
#include <cuda_pipeline.h>
#include <mma.h>
#include <stdint.h>

using namespace nvcuda;

#define N_NODES 10000
#define D 256
#define ROW_WORDS 320   // ceil(10000/32)=313, padded to 320 (1280 B/row)

// ---------------- scratch (device globals; no allocation allowed) ----------
// g_bitmap starts zero (module load) and is re-zeroed by spmm_kernel each call.
__device__ __align__(16) unsigned int g_bitmap[N_NODES * ROW_WORDS];  // 12.8 MB
__device__ int g_deg[N_NODES];                 // zeroed by prep each call
__device__ float g_dinv[N_NODES];
__device__ __align__(16) __half g_zs_h[N_NODES * D];   // fp16 dinv[j]*(x@W)[j,:]
__device__ __align__(16) __half g_xf[N_NODES * D];     // fp16 x [m][k]
__device__ __align__(16) __half g_wf[D * D];           // fp16 W [k][n]
__device__ int g_mode;   // 0 = int32 edge layout, 1 = raw int64 layout

// ---------------------------------------------------------------------------
// prep: x,W -> fp16; zero g_deg; block 0 detects edge layout.
__global__ void prep_kernel(const float* __restrict__ x, const float* __restrict__ w,
                            const int* __restrict__ ei, int n_words) {
    int idx = blockIdx.x * blockDim.x + threadIdx.x;
    const int NX4 = N_NODES * D / 4;   // 640000
    if (idx < NX4) {
        float4 v = ((const float4*)x)[idx];
        __half2 a = __floats2half2_rn(v.x, v.y);
        __half2 b = __floats2half2_rn(v.z, v.w);
        uint2 o;
        o.x = *(unsigned int*)&a;
        o.y = *(unsigned int*)&b;
        ((uint2*)g_xf)[idx] = o;
    }
    if (idx < D * D / 4) {             // 16384
        float4 v = ((const float4*)w)[idx];
        __half2 a = __floats2half2_rn(v.x, v.y);
        __half2 b = __floats2half2_rn(v.z, v.w);
        uint2 o;
        o.x = *(unsigned int*)&a;
        o.y = *(unsigned int*)&b;
        ((uint2*)g_wf)[idx] = o;
    }
    if (idx < N_NODES) g_deg[idx] = 0;

    if (blockIdx.x == 0) {
        __shared__ unsigned int s_or[8];
        int t = threadIdx.x;           // 256 threads check 512 odd words
        unsigned int v = 0;
        int i0 = 4 * t + 1, i1 = 4 * t + 3;
        if (i0 < n_words) v |= (unsigned int)ei[i0];
        if (i1 < n_words) v |= (unsigned int)ei[i1];
        #pragma unroll
        for (int o = 16; o > 0; o >>= 1) v |= __shfl_down_sync(0xffffffffu, v, o);
        if ((t & 31) == 0) s_or[t >> 5] = v;
        __syncthreads();
        if (t == 0) {
            unsigned int r = 0;
            #pragma unroll
            for (int w2 = 0; w2 < 8; w2++) r |= s_or[w2];
            g_mode = (r == 0u) ? 1 : 0;   // all-zero odd words => int64
        }
    }
}

// 2 edges per thread; atomicOr return gives exact dedup AND degree counting
__global__ void set_edges_kernel(const int* __restrict__ ei, int E) {
    int t = blockIdx.x * blockDim.x + threadIdx.x;
    int base = t * 2;
    if (base >= E) return;
    int s[2], d[2];
    bool vec = ((E & 1) == 0) && (base + 1 < E);
    if (g_mode) {
        if (vec) {
            int4 a = ((const int4*)ei)[t];
            int4 b = ((const int4*)(ei + 2 * E))[t];
            s[0] = a.x; s[1] = a.z;
            d[0] = b.x; d[1] = b.z;
        } else {
            #pragma unroll
            for (int q = 0; q < 2; q++) {
                int e = base + q;
                s[q] = (e < E) ? ei[2 * e] : -1;
                d[q] = (e < E) ? ei[2 * E + 2 * e] : -1;
            }
        }
    } else {
        if (vec) {
            int2 a = ((const int2*)ei)[t];
            int2 b = ((const int2*)(ei + E))[t];
            s[0] = a.x; s[1] = a.y;
            d[0] = b.x; d[1] = b.y;
        } else {
            #pragma unroll
            for (int q = 0; q < 2; q++) {
                int e = base + q;
                s[q] = (e < E) ? ei[e] : -1;
                d[q] = (e < E) ? ei[E + e] : -1;
            }
        }
    }
    #pragma unroll
    for (int q = 0; q < 2; q++) {
        if ((unsigned)s[q] < N_NODES && (unsigned)d[q] < N_NODES) {
            unsigned int b1 = 1u << (d[q] & 31);
            unsigned int o1 = atomicOr(&g_bitmap[s[q] * ROW_WORDS + (d[q] >> 5)], b1);
            if (!(o1 & b1)) atomicAdd(&g_deg[s[q]], 1);
            unsigned int b2 = 1u << (s[q] & 31);
            unsigned int o2 = atomicOr(&g_bitmap[d[q] * ROW_WORDS + (s[q] >> 5)], b2);
            if (!(o2 & b2)) atomicAdd(&g_deg[d[q]], 1);
        }
    }
}

__global__ void dinv_kernel() {
    int i = blockIdx.x * blockDim.x + threadIdx.x;
    if (i < N_NODES) g_dinv[i] = rsqrtf((float)(g_deg[i] + 1));
}

// ---------------------------------------------------------------------------
// Single-pass fp16 wmma GEMM, cp.async double-buffered:
//   zs[m,n] = fp16( dinv[m] * sum_k x[m,k] * W[k,n] ), f32 accumulate
// CTA tile 64x64, BK=32, 128 threads / 4 warps (2 M x 2 N), warp tile 32x32.
#define BKC 32
#define LDA 40    // 64 x 40 half (80 B/row)
#define LDB 72    // 32 x 72 half (144 B/row)
#define LDC 68    // 64 x 68 f32
#define A_BYTES (64 * LDA * 2)               // 5120
#define B_OFF   A_BYTES
#define BUF_BYTES (A_BYTES + 32 * LDB * 2)   // 9728
#define SMEM_GEMM (2 * BUF_BYTES)            // 19456 >= 64*68*4=17408 epilogue

__global__ __launch_bounds__(128, 6) void gemm_fp16_kernel() {
    extern __shared__ char smem[];
    float* sC = (float*)smem;

    int tid = threadIdx.x;
    int wid = tid >> 5;
    int warp_m = wid & 1;        // 0..1 (32 rows)
    int warp_n = wid >> 1;       // 0..1 (32 cols)
    int bm = blockIdx.x * 64;
    int bn = blockIdx.y * 64;

    wmma::fragment<wmma::accumulator, 16, 16, 16, float> acc[2][2];
    #pragma unroll
    for (int mi = 0; mi < 2; mi++)
        #pragma unroll
        for (int ni = 0; ni < 2; ni++)
            wmma::fill_fragment(acc[mi][ni], 0.0f);

    auto issue = [&](int buf, int k0) {
        char* base = smem + buf * BUF_BYTES;
        __half* sA = (__half*)base;
        __half* sB = (__half*)(base + B_OFF);
        // A: 64 rows x 32 half = 64 B/row = 4 x16B slots; row=lin>>2, q=lin&3
        #pragma unroll
        for (int t = 0; t < 2; t++) {
            int lin = tid + t * 128;
            int row = lin >> 2, q = lin & 3;
            int m = bm + row;
            size_t gi = (size_t)((m < N_NODES) ? m : 0) * D + k0 + q * 8;
            size_t zf = (m < N_NODES) ? 0 : 16;
            __pipeline_memcpy_async(&sA[row * LDA + q * 8], &g_xf[gi], 16, zf);
        }
        // B: 32 rows x 64 half = 128 B/row = 8 x16B slots; kr=lin>>3, nq=lin&7
        #pragma unroll
        for (int t = 0; t < 2; t++) {
            int lin = tid + t * 128;
            int kr = lin >> 3, nq = lin & 7;
            size_t gi = (size_t)(k0 + kr) * D + bn + nq * 8;
            __pipeline_memcpy_async(&sB[kr * LDB + nq * 8], &g_wf[gi], 16);
        }
    };

    issue(0, 0);
    __pipeline_commit();

    for (int kc = 0; kc < 8; kc++) {
        if (kc < 7) {
            issue((kc + 1) & 1, (kc + 1) * BKC);
            __pipeline_commit();
            __pipeline_wait_prior(1);
        } else {
            __pipeline_wait_prior(0);
        }
        __syncthreads();

        char* base = smem + (kc & 1) * BUF_BYTES;
        __half* sA = (__half*)base;
        __half* sB = (__half*)(base + B_OFF);

        #pragma unroll
        for (int kk = 0; kk < 32; kk += 16) {
            wmma::fragment<wmma::matrix_b, 16, 16, 16, __half, wmma::row_major> bfr[2];
            #pragma unroll
            for (int ni = 0; ni < 2; ni++)
                wmma::load_matrix_sync(bfr[ni], &sB[kk * LDB + warp_n * 32 + ni * 16], LDB);
            #pragma unroll
            for (int mi = 0; mi < 2; mi++) {
                wmma::fragment<wmma::matrix_a, 16, 16, 16, __half, wmma::row_major> afr;
                wmma::load_matrix_sync(afr, &sA[(warp_m * 32 + mi * 16) * LDA + kk], LDA);
                #pragma unroll
                for (int ni = 0; ni < 2; ni++)
                    wmma::mma_sync(acc[mi][ni], afr, bfr[ni], acc[mi][ni]);
            }
        }
        __syncthreads();
    }

    // Epilogue: frags -> smem -> scale by dinv -> g_zs_h (fp16)
    #pragma unroll
    for (int mi = 0; mi < 2; mi++)
        #pragma unroll
        for (int ni = 0; ni < 2; ni++)
            wmma::store_matrix_sync(
                &sC[(warp_m * 32 + mi * 16) * LDC + warp_n * 32 + ni * 16],
                acc[mi][ni], LDC, wmma::mem_row_major);
    __syncthreads();

    #pragma unroll
    for (int t = 0; t < 8; t++) {
        int lin = tid + t * 128;
        int row = lin >> 4, c4 = lin & 15;
        int m = bm + row;
        if (m < N_NODES) {
            float dv = g_dinv[m];
            float4 v = *(float4*)&sC[row * LDC + c4 * 4];
            __half2 h01 = __floats2half2_rn(v.x * dv, v.y * dv);
            __half2 h23 = __floats2half2_rn(v.z * dv, v.w * dv);
            uint2 o;
            o.x = *(unsigned int*)&h01;
            o.y = *(unsigned int*)&h23;
            *(uint2*)&g_zs_h[(size_t)m * D + bn + c4 * 4] = o;
        }
    }
}

// ---------------------------------------------------------------------------
// SpMM over the bitmap: out[i,:] = dinv[i] * (sum_{bit(i,j)} zs[j,:] + zs[i,:])
// Self-cleaning: zeroes each bitmap word after reading (next call starts clean).
#define SCHUNK 128
#define SCAP (SCHUNK * 32)

__global__ __launch_bounds__(128) void spmm_kernel(float* __restrict__ out) {
    __shared__ int s_idx[SCAP];
    __shared__ int s_cnt;
    int i = blockIdx.x;
    int t = threadIdx.x;                         // dim pair t -> dims 2t, 2t+1
    unsigned int* row = &g_bitmap[i * ROW_WORDS];
    const __half2* zs2 = (const __half2*)g_zs_h;

    float2 a0 = {0.f, 0.f}, a1 = {0.f, 0.f}, a2 = {0.f, 0.f}, a3 = {0.f, 0.f};

    for (int cw = 0; cw < ROW_WORDS; cw += SCHUNK) {
        if (t == 0) s_cnt = 0;
        __syncthreads();
        int w = cw + t;
        unsigned int bits = 0u;
        if (w < ROW_WORDS) {
            bits = row[w];
            if (bits) row[w] = 0u;               // self-clean for next call
        }
        while (bits) {
            int b = __ffs(bits) - 1;
            bits &= bits - 1;
            s_idx[atomicAdd(&s_cnt, 1)] = (w << 5) + b;
        }
        __syncthreads();
        int nb = s_cnt;
        int k = 0;
        for (; k + 4 <= nb; k += 4) {
            int j0 = s_idx[k + 0];
            int j1 = s_idx[k + 1];
            int j2 = s_idx[k + 2];
            int j3 = s_idx[k + 3];
            float2 v0 = __half22float2(zs2[(size_t)j0 * 128 + t]);
            float2 v1 = __half22float2(zs2[(size_t)j1 * 128 + t]);
            float2 v2 = __half22float2(zs2[(size_t)j2 * 128 + t]);
            float2 v3 = __half22float2(zs2[(size_t)j3 * 128 + t]);
            a0.x += v0.x; a0.y += v0.y;
            a1.x += v1.x; a1.y += v1.y;
            a2.x += v2.x; a2.y += v2.y;
            a3.x += v3.x; a3.y += v3.y;
        }
        for (; k < nb; k++) {
            float2 v = __half22float2(zs2[(size_t)s_idx[k] * 128 + t]);
            a0.x += v.x; a0.y += v.y;
        }
        __syncthreads();
    }

    float2 self = __half22float2(zs2[(size_t)i * 128 + t]);
    float dv = g_dinv[i];
    float2 r;
    r.x = dv * ((a0.x + a1.x) + (a2.x + a3.x) + self.x);
    r.y = dv * ((a0.y + a1.y) + (a2.y + a3.y) + self.y);
    ((float2*)out)[(size_t)i * 128 + t] = r;
}

// ---------------------------------------------------------------------------
extern "C" void kernel_launch(void* const* d_in, const int* in_sizes, int n_in,
                              void* d_out, int out_size) {
    const float* x = (const float*)d_in[0];
    const int* ei = (const int*)d_in[1];
    const float* w = (const float*)d_in[2];
    float* out = (float*)d_out;
    int E = in_sizes[1] / 2;

    cudaFuncSetAttribute(gemm_fp16_kernel,
                         cudaFuncAttributeMaxDynamicSharedMemorySize, SMEM_GEMM);

    prep_kernel<<<(N_NODES * D / 4 + 255) / 256, 256>>>(x, w, ei, 2 * E);
    set_edges_kernel<<<(E / 2 + 255) / 256, 256>>>(ei, E);
    dinv_kernel<<<(N_NODES + 255) / 256, 256>>>();

    dim3 ggrid((N_NODES + 63) / 64, D / 64);
    gemm_fp16_kernel<<<ggrid, 128, SMEM_GEMM>>>();

    spmm_kernel<<<N_NODES, 128>>>(out);
}